// round 11
// baseline (speedup 1.0000x reference)
#include <cuda_runtime.h>

#define IN_F 8192
#define OUT_F 8192
#define THRESH_F 50.0f
#define ROWS_PER_BLOCK 8
#define THREADS 256
#define MV_BLOCKS (OUT_F / ROWS_PER_BLOCK)    // 1024
#define EPI_BLOCKS 64                         // last 64 arrivals do epilogue
#define EPI_ROWS (OUT_F / EPI_BLOCKS)         // 128 rows per epilogue block

// Scratch (no allocations allowed). g_done is a MONOTONIC arrival counter:
// each launch adds exactly MV_BLOCKS (1024); 2^32 % 1024 == 0, so
// base = old & ~1023 is race-free across CUDA-graph replays.
__device__ float g_current[OUT_F];
__device__ __align__(16) float g_partial[MV_BLOCKS];
__device__ unsigned int g_done = 0;

// Fused kernel, R5-proven shape: 1024 blocks x 8 rows, natural registers
// (no min-blocks clause -> 6 blocks/SM, 48 warps; measured 42us incl drain).
__global__ void __launch_bounds__(THREADS) snn_fused_kernel(
    const float* __restrict__ spike_input,   // [IN_F]
    const float* __restrict__ syn,           // [OUT_F, IN_F] row-major
    const float* __restrict__ v_mem,         // [OUT_F]
    const float* __restrict__ v_th,          // [OUT_F]
    const float* __restrict__ noise,         // [OUT_F]
    float* __restrict__ out)                 // [spikes | v_mem_new | v_th_new]
{
    __shared__ float4 s_spike[IN_F / 4];     // 32 KB
    __shared__ float  s_spk[ROWS_PER_BLOCK];
    __shared__ float  s_red[THREADS / 32];
    __shared__ int    s_rank;

    const int tid = threadIdx.x;

    // Stage spike vector into shared (reused by all 8 rows in this block).
    const float4* sp4 = reinterpret_cast<const float4*>(spike_input);
    #pragma unroll
    for (int i = 0; i < (IN_F / 4) / THREADS; i++) {
        s_spike[tid + i * THREADS] = sp4[tid + i * THREADS];
    }
    __syncthreads();

    const int warp = tid >> 5;
    const int lane = tid & 31;
    const int row  = blockIdx.x * ROWS_PER_BLOCK + warp;

    const float4* r4 = reinterpret_cast<const float4*>(syn + (size_t)row * IN_F);

    float acc0 = 0.0f, acc1 = 0.0f;
    // Proven R2/R4/R5 body: 64 float4 per lane; 2 per iter, predicated adds.
    #pragma unroll 8
    for (int it = 0; it < (IN_F / 8) / 32; it++) {
        const int i0 = (it * 2 + 0) * 32 + lane;
        const int i1 = (it * 2 + 1) * 32 + lane;
        const float4 w0 = r4[i0];
        const float4 w1 = r4[i1];
        const float4 s0 = s_spike[i0];
        const float4 s1 = s_spike[i1];
        if (w0.x > THRESH_F) acc0 += s0.x;
        if (w0.y > THRESH_F) acc1 += s0.y;
        if (w0.z > THRESH_F) acc0 += s0.z;
        if (w0.w > THRESH_F) acc1 += s0.w;
        if (w1.x > THRESH_F) acc0 += s1.x;
        if (w1.y > THRESH_F) acc1 += s1.y;
        if (w1.z > THRESH_F) acc0 += s1.z;
        if (w1.w > THRESH_F) acc1 += s1.w;
    }
    float acc = acc0 + acc1;

    // Warp reduce (exact: small integers).
    #pragma unroll
    for (int o = 16; o > 0; o >>= 1) {
        acc += __shfl_xor_sync(0xFFFFFFFFu, acc, o);
    }

    if (lane == 0) {
        g_current[row] = acc;
        const float pot = v_mem[row] + acc + noise[row];
        const float spk = (pot >= v_th[row]) ? 1.0f : 0.0f;
        out[row] = spk;
        s_spk[warp] = spk;
    }
    __syncthreads();

    // ---- Arrival ticket; all but the last EPI_BLOCKS arrivals exit ----
    unsigned target = 0;
    if (tid == 0) {
        float p = 0.0f;
        #pragma unroll
        for (int w = 0; w < ROWS_PER_BLOCK; w++) p += s_spk[w];
        g_partial[blockIdx.x] = p;
        __threadfence();   // partial + g_current + spikes visible first
        const unsigned old = atomicAdd(&g_done, 1u);
        const unsigned base = old & ~(unsigned)(MV_BLOCKS - 1);
        s_rank = (int)(old - base);
        target = base + MV_BLOCKS;
    }
    __syncthreads();

    const int rank = s_rank;
    if (rank < MV_BLOCKS - EPI_BLOCKS) return;   // early blocks: done

    // ---- Last 64 arrivals: backoff-spin until all 1024 arrived ----
    if (tid == 0) {
        volatile unsigned* vd = &g_done;
        while ((int)(*vd - target) < 0) { __nanosleep(32); }
        __threadfence();   // acquire: order spin-read before epilogue loads
    }
    __syncthreads();

    // Inhibition: sum all 1024 L2-hot partials (exact integer sums).
    {
        const float4 p = __ldcg(reinterpret_cast<const float4*>(g_partial) + tid);
        float local = (p.x + p.y) + (p.z + p.w);
        #pragma unroll
        for (int o = 16; o > 0; o >>= 1) {
            local += __shfl_xor_sync(0xFFFFFFFFu, local, o);
        }
        if (lane == 0) s_red[warp] = local;
    }
    __syncthreads();

    float total = s_red[0];
    #pragma unroll
    for (int w = 1; w < THREADS / 32; w++) total += s_red[w];
    const float inhibition = total * 0.5f;

    // This block's 128 epilogue rows (tid < 128), sliced by arrival rank.
    // Spike recomputed with the IDENTICAL expression/order as the mainloop
    // ((vm + cur) + noise >= vth) -> bit-exact. g_current via __ldcg
    // (written by other blocks; avoid stale L1).
    if (tid < EPI_ROWS) {
        const int slice = rank - (MV_BLOCKS - EPI_BLOCKS);   // 0..63
        const int r = slice * EPI_ROWS + tid;

        const float cur = __ldcg(g_current + r);
        const float vm  = v_mem[r];
        const float vt0 = v_th[r];
        const float s   = ((vm + cur + noise[r]) >= vt0) ? 1.0f : 0.0f;

        out[OUT_F + r] = (vm - inhibition + cur) * (1.0f - s) * 0.5f;

        float vt = vt0 + (s - 0.1f) * 0.01f;
        out[2 * OUT_F + r] = fminf(fmaxf(vt, 0.2f), 5.0f);
    }
}

extern "C" void kernel_launch(void* const* d_in, const int* in_sizes, int n_in,
                              void* d_out, int out_size)
{
    const float* spike_input = (const float*)d_in[0];   // [1, 8192]
    const float* syn         = (const float*)d_in[1];   // [8192, 8192]
    const float* v_mem       = (const float*)d_in[2];   // [8192]
    const float* v_th        = (const float*)d_in[3];   // [8192]
    const float* noise       = (const float*)d_in[4];   // [8192]
    float* out = (float*)d_out;                          // 3 * 8192 floats

    snn_fused_kernel<<<MV_BLOCKS, THREADS>>>(
        spike_input, syn, v_mem, v_th, noise, out);
}

// round 12
// speedup vs baseline: 1.1962x; 1.1962x over previous
#include <cuda_runtime.h>

#define IN_F 8192
#define OUT_F 8192
#define THRESH_F 50.0f
#define ROWS_PER_BLOCK 8
#define THREADS 256
#define MV_BLOCKS (OUT_F / ROWS_PER_BLOCK)   // 1024
#define UPD_BLOCKS 256
#define UPD_THREADS 32

// Scratch between kernels (no allocations allowed). Fully overwritten every
// launch -> deterministic across graph replays.
__device__ float g_current[OUT_F];
__device__ __align__(16) float g_partial[MV_BLOCKS];   // per-block spike counts

// Kernel 1: binarized matvec + spike decision + per-block spike partial.
// R6-identical EXCEPT the syn stream is loaded with __ldcs (evict-first):
// the 268MB stream otherwise flushes L2 and makes kernel 2's loads cold.
__global__ void __launch_bounds__(THREADS) snn_matvec_kernel(
    const float* __restrict__ spike_input,   // [IN_F]
    const float* __restrict__ syn,           // [OUT_F, IN_F] row-major
    const float* __restrict__ v_mem,         // [OUT_F]
    const float* __restrict__ v_th,          // [OUT_F]
    const float* __restrict__ noise,         // [OUT_F]
    float* __restrict__ out)                 // out[0:OUT_F] = spikes
{
    __shared__ float4 s_spike[IN_F / 4];     // 32 KB
    __shared__ float  s_spk[ROWS_PER_BLOCK];

    const int tid = threadIdx.x;

    // Stage spike vector into shared (reused by all 8 rows in this block).
    const float4* sp4 = reinterpret_cast<const float4*>(spike_input);
    #pragma unroll
    for (int i = 0; i < (IN_F / 4) / THREADS; i++) {
        s_spike[tid + i * THREADS] = sp4[tid + i * THREADS];
    }
    __syncthreads();

    const int warp = tid >> 5;
    const int lane = tid & 31;
    const int row  = blockIdx.x * ROWS_PER_BLOCK + warp;

    const float4* r4 = reinterpret_cast<const float4*>(syn + (size_t)row * IN_F);

    float acc0 = 0.0f, acc1 = 0.0f;
    // 2048 float4 per row / 32 lanes = 64 float4 per lane; 2 per iteration.
    #pragma unroll 8
    for (int it = 0; it < (IN_F / 8) / 32; it++) {
        const int i0 = (it * 2 + 0) * 32 + lane;
        const int i1 = (it * 2 + 1) * 32 + lane;
        const float4 w0 = __ldcs(&r4[i0]);   // streaming, evict-first
        const float4 w1 = __ldcs(&r4[i1]);
        const float4 s0 = s_spike[i0];
        const float4 s1 = s_spike[i1];
        if (w0.x > THRESH_F) acc0 += s0.x;
        if (w0.y > THRESH_F) acc1 += s0.y;
        if (w0.z > THRESH_F) acc0 += s0.z;
        if (w0.w > THRESH_F) acc1 += s0.w;
        if (w1.x > THRESH_F) acc0 += s1.x;
        if (w1.y > THRESH_F) acc1 += s1.y;
        if (w1.z > THRESH_F) acc0 += s1.z;
        if (w1.w > THRESH_F) acc1 += s1.w;
    }
    float acc = acc0 + acc1;

    // Warp reduce (exact: small integers).
    #pragma unroll
    for (int o = 16; o > 0; o >>= 1) {
        acc += __shfl_xor_sync(0xFFFFFFFFu, acc, o);
    }

    if (lane == 0) {
        g_current[row] = acc;
        const float pot = v_mem[row] + acc + noise[row];
        const float spk = (pot >= v_th[row]) ? 1.0f : 0.0f;
        out[row] = spk;
        s_spk[warp] = spk;
    }
    __syncthreads();

    if (tid == 0) {
        float p = 0.0f;
        #pragma unroll
        for (int w = 0; w < ROWS_PER_BLOCK; w++) p += s_spk[w];
        g_partial[blockIdx.x] = p;
    }
}

// Kernel 2: PDL-launched. Independent loads before the grid dependency wait,
// dependent reads after. 256 blocks x 32 threads (one warp, no smem).
__global__ void __launch_bounds__(UPD_THREADS) snn_update_kernel(
    const float* __restrict__ v_mem,
    const float* __restrict__ v_th,
    float* __restrict__ out)   // [spikes | v_mem_new | v_th_new]
{
    const int tid = threadIdx.x;   // 0..31
    const int o   = blockIdx.x * UPD_THREADS + tid;

    // Independent of the matvec: issue before the grid dependency wait.
    const float vm  = v_mem[o];
    const float vt0 = v_th[o];

#if __CUDA_ARCH__ >= 900
    cudaGridDependencySynchronize();
#endif

    // Dependent loads (L2-hot if __ldcs preserved residency).
    const float s   = out[o];
    const float cur = g_current[o];

    // 1024 partials = 256 float4; 8 float4 per lane, coalesced, L2-hot.
    const float4* p4 = reinterpret_cast<const float4*>(g_partial);
    float local = 0.0f;
    #pragma unroll
    for (int i = 0; i < 8; i++) {
        const float4 a = p4[tid + i * 32];
        local += (a.x + a.y) + (a.z + a.w);
    }
    #pragma unroll
    for (int off = 16; off > 0; off >>= 1) {
        local += __shfl_xor_sync(0xFFFFFFFFu, local, off);
    }

    const float inhibition = local * 0.5f;

    const float v_new = (vm - inhibition + cur) * (1.0f - s) * 0.5f;

    float vt = vt0 + (s - 0.1f) * 0.01f;
    vt = fminf(fmaxf(vt, 0.2f), 5.0f);

    out[OUT_F + o]     = v_new;
    out[2 * OUT_F + o] = vt;
}

extern "C" void kernel_launch(void* const* d_in, const int* in_sizes, int n_in,
                              void* d_out, int out_size)
{
    const float* spike_input = (const float*)d_in[0];   // [1, 8192]
    const float* syn         = (const float*)d_in[1];   // [8192, 8192]
    const float* v_mem       = (const float*)d_in[2];   // [8192]
    const float* v_th        = (const float*)d_in[3];   // [8192]
    const float* noise       = (const float*)d_in[4];   // [8192]
    float* out = (float*)d_out;                          // 3 * 8192 floats

    snn_matvec_kernel<<<MV_BLOCKS, THREADS>>>(
        spike_input, syn, v_mem, v_th, noise, out);

    cudaLaunchAttribute attrs[1];
    attrs[0].id = cudaLaunchAttributeProgrammaticStreamSerialization;
    attrs[0].val.programmaticStreamSerializationAllowed = 1;

    cudaLaunchConfig_t cfg = {};
    cfg.gridDim  = dim3(UPD_BLOCKS, 1, 1);
    cfg.blockDim = dim3(UPD_THREADS, 1, 1);
    cfg.dynamicSmemBytes = 0;
    cfg.stream = 0;
    cfg.attrs = attrs;
    cfg.numAttrs = 1;
    cudaLaunchKernelEx(&cfg, snn_update_kernel, v_mem, v_th, (float*)out);
}

// round 13
// speedup vs baseline: 1.2017x; 1.0047x over previous
#include <cuda_runtime.h>

#define IN_F 8192
#define OUT_F 8192
#define THRESH_F 50.0f
#define ROWS_PER_BLOCK 8
#define THREADS 256
#define MV_BLOCKS (OUT_F / ROWS_PER_BLOCK)    // 1024
#define EPI_BLOCKS 64                         // last 64 arrivals do epilogue
#define EPI_ROWS (OUT_F / EPI_BLOCKS)         // 128 rows per epilogue block

// Scratch (no allocations allowed). g_done is a MONOTONIC arrival counter:
// each launch adds exactly MV_BLOCKS (1024); 2^32 % 1024 == 0, so
// base = old & ~1023 is race-free across CUDA-graph replays.
__device__ float g_current[OUT_F];
__device__ __align__(16) float g_partial[MV_BLOCKS];
__device__ unsigned int g_done = 0;

// Epilogue behind an ABI call: keeps its code OUT of the mainloop's
// register-allocation/scheduling region (the diagnosed cause of the bad
// 40-reg mainloop compiles in R5/R9/R11).
__device__ __noinline__ void snn_epilogue(
    int rank, float* s_red,
    const float* __restrict__ v_mem,
    const float* __restrict__ v_th,
    const float* __restrict__ noise,
    float* __restrict__ out)
{
    const int tid  = threadIdx.x;
    const int warp = tid >> 5;
    const int lane = tid & 31;

    // Inhibition: sum all 1024 L2-hot partials (exact integer sums).
    {
        const float4 p = __ldcg(reinterpret_cast<const float4*>(g_partial) + tid);
        float local = (p.x + p.y) + (p.z + p.w);
        #pragma unroll
        for (int o = 16; o > 0; o >>= 1) {
            local += __shfl_xor_sync(0xFFFFFFFFu, local, o);
        }
        if (lane == 0) s_red[warp] = local;
    }
    __syncthreads();

    float total = s_red[0];
    #pragma unroll
    for (int w = 1; w < THREADS / 32; w++) total += s_red[w];
    const float inhibition = total * 0.5f;

    // This block's 128 rows (tid < 128), sliced by arrival rank. Spike is
    // recomputed with the IDENTICAL expression/order as the mainloop
    // ((vm + cur) + noise >= vth) -> bit-exact. g_current via __ldcg
    // (written by other blocks; avoid stale L1).
    if (tid < EPI_ROWS) {
        const int slice = rank - (MV_BLOCKS - EPI_BLOCKS);   // 0..63
        const int r = slice * EPI_ROWS + tid;

        const float cur = __ldcg(g_current + r);
        const float vm  = v_mem[r];
        const float vt0 = v_th[r];
        const float s   = ((vm + cur + noise[r]) >= vt0) ? 1.0f : 0.0f;

        out[OUT_F + r] = (vm - inhibition + cur) * (1.0f - s) * 0.5f;

        float vt = vt0 + (s - 0.1f) * 0.01f;
        out[2 * OUT_F + r] = fminf(fmaxf(vt, 0.2f), 5.0f);
    }
}

// Fused kernel: R6-matvec body verbatim + arrival ticket; last 64 arrivals
// spin briefly and run the (noinline) epilogue. Natural registers.
__global__ void __launch_bounds__(THREADS) snn_fused_kernel(
    const float* __restrict__ spike_input,   // [IN_F]
    const float* __restrict__ syn,           // [OUT_F, IN_F] row-major
    const float* __restrict__ v_mem,         // [OUT_F]
    const float* __restrict__ v_th,          // [OUT_F]
    const float* __restrict__ noise,         // [OUT_F]
    float* __restrict__ out)                 // [spikes | v_mem_new | v_th_new]
{
    __shared__ float4 s_spike[IN_F / 4];     // 32 KB
    __shared__ float  s_spk[ROWS_PER_BLOCK];
    __shared__ float  s_red[THREADS / 32];
    __shared__ int    s_rank;

    const int tid = threadIdx.x;

    // Stage spike vector into shared (reused by all 8 rows in this block).
    const float4* sp4 = reinterpret_cast<const float4*>(spike_input);
    #pragma unroll
    for (int i = 0; i < (IN_F / 4) / THREADS; i++) {
        s_spike[tid + i * THREADS] = sp4[tid + i * THREADS];
    }
    __syncthreads();

    const int warp = tid >> 5;
    const int lane = tid & 31;
    const int row  = blockIdx.x * ROWS_PER_BLOCK + warp;

    const float4* r4 = reinterpret_cast<const float4*>(syn + (size_t)row * IN_F);

    float acc0 = 0.0f, acc1 = 0.0f;
    // Proven R2/R4/R6 body: 64 float4 per lane; 2 per iter, predicated adds.
    #pragma unroll 8
    for (int it = 0; it < (IN_F / 8) / 32; it++) {
        const int i0 = (it * 2 + 0) * 32 + lane;
        const int i1 = (it * 2 + 1) * 32 + lane;
        const float4 w0 = r4[i0];
        const float4 w1 = r4[i1];
        const float4 s0 = s_spike[i0];
        const float4 s1 = s_spike[i1];
        if (w0.x > THRESH_F) acc0 += s0.x;
        if (w0.y > THRESH_F) acc1 += s0.y;
        if (w0.z > THRESH_F) acc0 += s0.z;
        if (w0.w > THRESH_F) acc1 += s0.w;
        if (w1.x > THRESH_F) acc0 += s1.x;
        if (w1.y > THRESH_F) acc1 += s1.y;
        if (w1.z > THRESH_F) acc0 += s1.z;
        if (w1.w > THRESH_F) acc1 += s1.w;
    }
    float acc = acc0 + acc1;

    // Warp reduce (exact: small integers).
    #pragma unroll
    for (int o = 16; o > 0; o >>= 1) {
        acc += __shfl_xor_sync(0xFFFFFFFFu, acc, o);
    }

    if (lane == 0) {
        g_current[row] = acc;
        const float pot = v_mem[row] + acc + noise[row];
        const float spk = (pot >= v_th[row]) ? 1.0f : 0.0f;
        out[row] = spk;
        s_spk[warp] = spk;
    }
    __syncthreads();

    // ---- Publish partial + arrival ticket ----
    unsigned target = 0;
    if (tid == 0) {
        float p = 0.0f;
        #pragma unroll
        for (int w = 0; w < ROWS_PER_BLOCK; w++) p += s_spk[w];
        g_partial[blockIdx.x] = p;
        __threadfence();   // partial + g_current + spikes visible first
        const unsigned old = atomicAdd(&g_done, 1u);
        const unsigned base = old & ~(unsigned)(MV_BLOCKS - 1);
        s_rank = (int)(old - base);
        target = base + MV_BLOCKS;
    }
    __syncthreads();

    const int rank = s_rank;
    if (rank < MV_BLOCKS - EPI_BLOCKS) return;   // 960 early blocks: done

    // ---- Last 64 arrivals: backoff-spin until all 1024 arrived ----
    if (tid == 0) {
        volatile unsigned* vd = &g_done;
        while ((int)(*vd - target) < 0) { __nanosleep(32); }
        __threadfence();   // acquire: order spin-read before epilogue loads
    }
    __syncthreads();

    snn_epilogue(rank, s_red, v_mem, v_th, noise, out);
}

extern "C" void kernel_launch(void* const* d_in, const int* in_sizes, int n_in,
                              void* d_out, int out_size)
{
    const float* spike_input = (const float*)d_in[0];   // [1, 8192]
    const float* syn         = (const float*)d_in[1];   // [8192, 8192]
    const float* v_mem       = (const float*)d_in[2];   // [8192]
    const float* v_th        = (const float*)d_in[3];   // [8192]
    const float* noise       = (const float*)d_in[4];   // [8192]
    float* out = (float*)d_out;                          // 3 * 8192 floats

    snn_fused_kernel<<<MV_BLOCKS, THREADS>>>(
        spike_input, syn, v_mem, v_th, noise, out);
}

// round 14
// speedup vs baseline: 1.2262x; 1.0204x over previous
#include <cuda_runtime.h>

#define IN_F 8192
#define OUT_F 8192
#define THRESH_F 50.0f
#define ROWS_PER_BLOCK 8
#define THREADS 256
#define MV_BLOCKS (OUT_F / ROWS_PER_BLOCK)   // 1024
#define UPD_BLOCKS 256
#define UPD_THREADS 32

// Scratch between kernels (no allocations allowed). Fully overwritten every
// launch -> deterministic across graph replays.
__device__ float g_current[OUT_F];
__device__ __align__(16) float g_partial[MV_BLOCKS];   // per-block spike counts

// Kernel 1: binarized matvec + spike decision + per-block spike partial.
// Proven champion body (measured 47.136us twice): natural registers (40),
// 6 blocks/SM, ~6.4 TB/s on the 268MB synapse stream. DO NOT MUTATE:
// reg caps (R3/R9), __ldcs (R12), fusion (R5/R8/R9/R10/R11/R13) all
// measured neutral-or-worse.
__global__ void __launch_bounds__(THREADS) snn_matvec_kernel(
    const float* __restrict__ spike_input,   // [IN_F]
    const float* __restrict__ syn,           // [OUT_F, IN_F] row-major
    const float* __restrict__ v_mem,         // [OUT_F]
    const float* __restrict__ v_th,          // [OUT_F]
    const float* __restrict__ noise,         // [OUT_F]
    float* __restrict__ out)                 // out[0:OUT_F] = spikes
{
    __shared__ float4 s_spike[IN_F / 4];     // 32 KB
    __shared__ float  s_spk[ROWS_PER_BLOCK];

    const int tid = threadIdx.x;

    // Stage spike vector into shared (reused by all 8 rows in this block).
    const float4* sp4 = reinterpret_cast<const float4*>(spike_input);
    #pragma unroll
    for (int i = 0; i < (IN_F / 4) / THREADS; i++) {
        s_spike[tid + i * THREADS] = sp4[tid + i * THREADS];
    }
    __syncthreads();

    const int warp = tid >> 5;
    const int lane = tid & 31;
    const int row  = blockIdx.x * ROWS_PER_BLOCK + warp;

    const float4* r4 = reinterpret_cast<const float4*>(syn + (size_t)row * IN_F);

    float acc0 = 0.0f, acc1 = 0.0f;
    // 2048 float4 per row / 32 lanes = 64 float4 per lane; 2 per iteration.
    #pragma unroll 8
    for (int it = 0; it < (IN_F / 8) / 32; it++) {
        const int i0 = (it * 2 + 0) * 32 + lane;
        const int i1 = (it * 2 + 1) * 32 + lane;
        const float4 w0 = r4[i0];
        const float4 w1 = r4[i1];
        const float4 s0 = s_spike[i0];
        const float4 s1 = s_spike[i1];
        if (w0.x > THRESH_F) acc0 += s0.x;
        if (w0.y > THRESH_F) acc1 += s0.y;
        if (w0.z > THRESH_F) acc0 += s0.z;
        if (w0.w > THRESH_F) acc1 += s0.w;
        if (w1.x > THRESH_F) acc0 += s1.x;
        if (w1.y > THRESH_F) acc1 += s1.y;
        if (w1.z > THRESH_F) acc0 += s1.z;
        if (w1.w > THRESH_F) acc1 += s1.w;
    }
    float acc = acc0 + acc1;

    // Warp reduce (exact: small integers).
    #pragma unroll
    for (int o = 16; o > 0; o >>= 1) {
        acc += __shfl_xor_sync(0xFFFFFFFFu, acc, o);
    }

    if (lane == 0) {
        g_current[row] = acc;
        const float pot = v_mem[row] + acc + noise[row];
        const float spk = (pot >= v_th[row]) ? 1.0f : 0.0f;
        out[row] = spk;
        s_spk[warp] = spk;
    }
    __syncthreads();

    if (tid == 0) {
        float p = 0.0f;
        #pragma unroll
        for (int w = 0; w < ROWS_PER_BLOCK; w++) p += s_spk[w];
        g_partial[blockIdx.x] = p;
    }
}

// Kernel 2: PDL-launched. Independent loads before the grid dependency wait,
// dependent reads after. 256 blocks x 32 threads (one warp, no smem).
// ~5us = fixed node/dispatch overhead (invariant across 5 shapes, PDL,
// cache policy) — accepted as floor.
__global__ void __launch_bounds__(UPD_THREADS) snn_update_kernel(
    const float* __restrict__ v_mem,
    const float* __restrict__ v_th,
    float* __restrict__ out)   // [spikes | v_mem_new | v_th_new]
{
    const int tid = threadIdx.x;   // 0..31
    const int o   = blockIdx.x * UPD_THREADS + tid;

    // Independent of the matvec: issue before the grid dependency wait.
    const float vm  = v_mem[o];
    const float vt0 = v_th[o];

#if __CUDA_ARCH__ >= 900
    cudaGridDependencySynchronize();
#endif

    // Dependent loads.
    const float s   = out[o];
    const float cur = g_current[o];

    // 1024 partials = 256 float4; 8 float4 per lane, coalesced, L2-hot.
    const float4* p4 = reinterpret_cast<const float4*>(g_partial);
    float local = 0.0f;
    #pragma unroll
    for (int i = 0; i < 8; i++) {
        const float4 a = p4[tid + i * 32];
        local += (a.x + a.y) + (a.z + a.w);
    }
    #pragma unroll
    for (int off = 16; off > 0; off >>= 1) {
        local += __shfl_xor_sync(0xFFFFFFFFu, local, off);
    }

    const float inhibition = local * 0.5f;

    const float v_new = (vm - inhibition + cur) * (1.0f - s) * 0.5f;

    float vt = vt0 + (s - 0.1f) * 0.01f;
    vt = fminf(fmaxf(vt, 0.2f), 5.0f);

    out[OUT_F + o]     = v_new;
    out[2 * OUT_F + o] = vt;
}

extern "C" void kernel_launch(void* const* d_in, const int* in_sizes, int n_in,
                              void* d_out, int out_size)
{
    const float* spike_input = (const float*)d_in[0];   // [1, 8192]
    const float* syn         = (const float*)d_in[1];   // [8192, 8192]
    const float* v_mem       = (const float*)d_in[2];   // [8192]
    const float* v_th        = (const float*)d_in[3];   // [8192]
    const float* noise       = (const float*)d_in[4];   // [8192]
    float* out = (float*)d_out;                          // 3 * 8192 floats

    snn_matvec_kernel<<<MV_BLOCKS, THREADS>>>(
        spike_input, syn, v_mem, v_th, noise, out);

    // PDL: overlap update-kernel ramp with the matvec tail (measured
    // harmless; occasionally hides part of the node gap).
    cudaLaunchAttribute attrs[1];
    attrs[0].id = cudaLaunchAttributeProgrammaticStreamSerialization;
    attrs[0].val.programmaticStreamSerializationAllowed = 1;

    cudaLaunchConfig_t cfg = {};
    cfg.gridDim  = dim3(UPD_BLOCKS, 1, 1);
    cfg.blockDim = dim3(UPD_THREADS, 1, 1);
    cfg.dynamicSmemBytes = 0;
    cfg.stream = 0;
    cfg.attrs = attrs;
    cfg.numAttrs = 1;
    cudaLaunchKernelEx(&cfg, snn_update_kernel, v_mem, v_th, (float*)out);
}